// round 1
// baseline (speedup 1.0000x reference)
#include <cuda_runtime.h>

#define NB 8
#define NL 256
#define NF 6272
#define NU 32

// Scratch (no cudaMalloc allowed): p = inputs@Wt  [B*L, U]; a = softmax weights [B, L, L]
__device__ float g_p[NB*NL*NU];
__device__ float g_a[NB*NL*NL];

__device__ __forceinline__ float tanh_approx(float x){
    float y; asm("tanh.approx.f32 %0, %1;" : "=f"(y) : "f"(x)); return y;
}

// ---------------------------------------------------------------------------
// K1: p[b*l, u] = sum_f inputs[b,l,f] * Wt[f,u]
// grid = B*L/8 blocks, 256 threads. warp = row, lane = u.
// ---------------------------------------------------------------------------
__global__ __launch_bounds__(256) void k_proj(const float* __restrict__ inp,
                                              const float* __restrict__ Wt){
    __shared__ float wts[64][32];   // [j][u] — chunk of Wt, same layout as global
    __shared__ float xs[8][64];     // [row][j]
    const int t = threadIdx.x;
    const int r = t >> 5;           // warp index = row within block (8 rows)
    const int u = t & 31;           // lane = unit
    const int row0 = blockIdx.x * 8;

    float acc = 0.f;
    for (int f0 = 0; f0 < NF; f0 += 64){
        // Stage Wt chunk: rows f0..f0+63 are 2048 contiguous floats.
        {
            const float4* src = (const float4*)(Wt + f0*NU);
            float4* dst = (float4*)&wts[0][0];
            dst[t]       = src[t];
            dst[t + 256] = src[t + 256];
        }
        // Stage x chunk: 8 rows x 64 floats (128 float4, threads 0..127)
        if (t < 128){
            int rr = t >> 4, c4 = t & 15;
            *(float4*)&xs[rr][c4*4] = *(const float4*)(inp + (size_t)(row0+rr)*NF + f0 + c4*4);
        }
        __syncthreads();
        #pragma unroll
        for (int j = 0; j < 64; j += 4){
            float4 xv = *(const float4*)&xs[r][j];  // warp-uniform broadcast
            acc = fmaf(xv.x, wts[j+0][u], acc);
            acc = fmaf(xv.y, wts[j+1][u], acc);
            acc = fmaf(xv.z, wts[j+2][u], acc);
            acc = fmaf(xv.w, wts[j+3][u], acc);
        }
        __syncthreads();
    }
    g_p[(row0 + r)*NU + u] = acc;
}

// ---------------------------------------------------------------------------
// K2: a[b,q,k] = softmax_k( sigmoid( sum_u Wa[u]*tanh(p[b,q,u]+p[b,k,u]+bh[u]) + ba ) )
// grid = B*L blocks (one per (b,q)), 256 threads (thread = k).
// ---------------------------------------------------------------------------
__global__ __launch_bounds__(256) void k_attn(const float* __restrict__ bh,
                                              const float* __restrict__ Wa,
                                              const float* __restrict__ ba){
    __shared__ float ps[NL][33];   // p tile for batch b, padded (bank = (k+u)%32)
    __shared__ float pqb[32];      // p[b,q,:] + bh
    __shared__ float was[32];
    __shared__ float red[8];
    __shared__ float s_inv_total;

    const int t = threadIdx.x;
    const int b = blockIdx.x >> 8;
    const int q = blockIdx.x & 255;
    const float* pb = g_p + b*NL*NU;

    #pragma unroll
    for (int i = 0; i < 32; i++){
        int idx = t + i*256;
        ps[idx >> 5][idx & 31] = pb[idx];
    }
    if (t < 32){
        was[t] = Wa[t];
        pqb[t] = pb[q*NU + t] + bh[t];
    }
    __syncthreads();

    float acc = 0.f;
    #pragma unroll
    for (int u = 0; u < 32; u++){
        acc = fmaf(was[u], tanh_approx(pqb[u] + ps[t][u]), acc);
    }
    float alpha = acc + ba[0];
    float s = 1.f / (1.f + __expf(-alpha));   // sigmoid
    float e = __expf(s);                      // s in (0,1): no max-subtraction needed

    // block reduction of sum(e)
    float w = e;
    #pragma unroll
    for (int o = 16; o > 0; o >>= 1) w += __shfl_xor_sync(0xffffffffu, w, o);
    if ((t & 31) == 0) red[t >> 5] = w;
    __syncthreads();
    if (t == 0){
        float tot = 0.f;
        #pragma unroll
        for (int i = 0; i < 8; i++) tot += red[i];
        s_inv_total = 1.f / tot;
    }
    __syncthreads();

    g_a[b*NL*NL + q*NL + t] = e * s_inv_total;
}

// ---------------------------------------------------------------------------
// K3: out[b,q,f] = sum_k a[b,q,k] * inputs[b,k,f]
// Tiled fp32 GEMM per batch: BM=64, BN=128, BK=16, 256 threads, 8x4 micro-tile.
// grid = (F/128, L/64, B)
// ---------------------------------------------------------------------------
__global__ __launch_bounds__(256) void k_out(const float* __restrict__ inp,
                                             float* __restrict__ out){
    __shared__ float As[64][16];    // [m][kk] — reads are warp-uniform broadcasts
    __shared__ float Bs[16][128];   // [kk][f]
    const int t  = threadIdx.x;
    const int tx = t & 31;          // f-group: f = f0 + tx*4
    const int ty = t >> 5;          // q-group: q = q0 + ty*8
    const int b  = blockIdx.z;
    const int q0 = blockIdx.y * 64;
    const int f0 = blockIdx.x * 128;
    const float* ab = g_a + b*NL*NL;
    const float* xb = inp + (size_t)b*NL*NF;

    float acc[8][4];
    #pragma unroll
    for (int i = 0; i < 8; i++)
        #pragma unroll
        for (int j = 0; j < 4; j++) acc[i][j] = 0.f;

    for (int k0 = 0; k0 < NL; k0 += 16){
        // Stage A: 64 q-rows x 16 k — 256 float4, one per thread
        {
            int m = t >> 2, kg = t & 3;
            *(float4*)&As[m][kg*4] = *(const float4*)(ab + (q0+m)*NL + k0 + kg*4);
        }
        // Stage B: 16 k-rows x 128 f — 512 float4, two per thread
        #pragma unroll
        for (int i = 0; i < 2; i++){
            int idx4 = t + i*256;
            int kk = idx4 >> 5, f4 = idx4 & 31;
            *(float4*)&Bs[kk][f4*4] = *(const float4*)(xb + (size_t)(k0+kk)*NF + f0 + f4*4);
        }
        __syncthreads();

        #pragma unroll
        for (int kk = 0; kk < 16; kk++){
            float4 bv = *(const float4*)&Bs[kk][tx*4];   // conflict-free
            float ar[8];
            #pragma unroll
            for (int i = 0; i < 8; i++) ar[i] = As[ty*8 + i][kk];  // broadcast
            #pragma unroll
            for (int i = 0; i < 8; i++){
                acc[i][0] = fmaf(ar[i], bv.x, acc[i][0]);
                acc[i][1] = fmaf(ar[i], bv.y, acc[i][1]);
                acc[i][2] = fmaf(ar[i], bv.z, acc[i][2]);
                acc[i][3] = fmaf(ar[i], bv.w, acc[i][3]);
            }
        }
        __syncthreads();
    }

    #pragma unroll
    for (int i = 0; i < 8; i++){
        float4 v = make_float4(acc[i][0], acc[i][1], acc[i][2], acc[i][3]);
        *(float4*)(out + (size_t)(b*NL + q0 + ty*8 + i)*NF + f0 + tx*4) = v;
    }
}

// ---------------------------------------------------------------------------
extern "C" void kernel_launch(void* const* d_in, const int* in_sizes, int n_in,
                              void* d_out, int out_size){
    const float* inp = (const float*)d_in[0];  // [B, L, F]
    const float* Wt  = (const float*)d_in[1];  // [F, U]
    const float* bh  = (const float*)d_in[2];  // [U]
    const float* Wa  = (const float*)d_in[3];  // [U, 1]
    const float* ba  = (const float*)d_in[4];  // [1]
    float* out = (float*)d_out;                // [B, L, F]

    k_proj<<<NB*NL/8, 256>>>(inp, Wt);
    k_attn<<<NB*NL, 256>>>(bh, Wa, ba);
    dim3 g3(NF/128, NL/64, NB);
    k_out<<<g3, 256>>>(inp, out);
}

// round 3
// speedup vs baseline: 2.2785x; 2.2785x over previous
#include <cuda_runtime.h>
#include <cuda_bf16.h>
#include <cstdint>

#define NB 8
#define NL 256
#define NF 6272
#define NU 32
#define KSPLIT 14

// Scratch (no cudaMalloc allowed)
__device__ float g_p[NB*NL*NU];                      // reduced projections
__device__ float g_pp[KSPLIT*NB*NL*NU];              // projection partials (deterministic)
__device__ __nv_bfloat16 g_ah[NB*NL*NL], g_al[NB*NL*NL];         // a hi/lo [b][q][k]
__device__ __nv_bfloat16 g_xh[(size_t)NB*NL*NF];                 // inputs hi [b][k][f]
__device__ __nv_bfloat16 g_xl[(size_t)NB*NL*NF];                 // inputs lo [b][k][f]

// ---------------------------------------------------------------------------
// helpers
// ---------------------------------------------------------------------------
__device__ __forceinline__ uint32_t s2u(const void* p){
    uint32_t a;
    asm("{ .reg .u64 t; cvta.to.shared.u64 t, %1; cvt.u32.u64 %0, t; }" : "=r"(a) : "l"(p));
    return a;
}
__device__ __forceinline__ float tanh_approx(float x){
    float y; asm("tanh.approx.f32 %0, %1;" : "=f"(y) : "f"(x)); return y;
}
__device__ __forceinline__ void ldsm4(uint32_t r[4], uint32_t a){
    asm volatile("ldmatrix.sync.aligned.m8n8.x4.shared.b16 {%0,%1,%2,%3}, [%4];"
                 : "=r"(r[0]), "=r"(r[1]), "=r"(r[2]), "=r"(r[3]) : "r"(a));
}
__device__ __forceinline__ void ldsm4t(uint32_t r[4], uint32_t a){
    asm volatile("ldmatrix.sync.aligned.m8n8.x4.trans.shared.b16 {%0,%1,%2,%3}, [%4];"
                 : "=r"(r[0]), "=r"(r[1]), "=r"(r[2]), "=r"(r[3]) : "r"(a));
}
__device__ __forceinline__ void mma_bf16(float c[4], const uint32_t a[4], uint32_t b0, uint32_t b1){
    asm volatile(
        "mma.sync.aligned.m16n8k16.row.col.f32.bf16.bf16.f32 "
        "{%0,%1,%2,%3}, {%4,%5,%6,%7}, {%8,%9}, {%0,%1,%2,%3};"
        : "+f"(c[0]), "+f"(c[1]), "+f"(c[2]), "+f"(c[3])
        : "r"(a[0]), "r"(a[1]), "r"(a[2]), "r"(a[3]), "r"(b0), "r"(b1));
}
__device__ __forceinline__ void split_bf16(float v, __nv_bfloat16& h, __nv_bfloat16& l){
    h = __float2bfloat16(v);
    l = __float2bfloat16(v - __bfloat162float(h));
}

// ---------------------------------------------------------------------------
// K_conv: elementwise bf16 hi/lo split of inputs (layout preserved [b][k][f])
// ---------------------------------------------------------------------------
__global__ __launch_bounds__(256) void k_conv(const float* __restrict__ inp){
    size_t i4 = (size_t)blockIdx.x*256 + threadIdx.x;   // float4 index
    float4 v = ((const float4*)inp)[i4];
    __nv_bfloat16 h[4], l[4];
    split_bf16(v.x, h[0], l[0]);
    split_bf16(v.y, h[1], l[1]);
    split_bf16(v.z, h[2], l[2]);
    split_bf16(v.w, h[3], l[3]);
    *(uint2*)&g_xh[i4*4] = *(uint2*)h;
    *(uint2*)&g_xl[i4*4] = *(uint2*)l;
}

// ---------------------------------------------------------------------------
// K_proj: p_partial[by] = x[rows, fchunk] @ Wt[fchunk, 32]  (bf16 split HMMA)
// grid (16, 14), 256 threads. Each warp: m16 x n32. BK=32 staged.
// ---------------------------------------------------------------------------
__global__ __launch_bounds__(256) void k_proj(const float* __restrict__ Wt){
    __shared__ __nv_bfloat16 Ah[128][40], Al[128][40];
    __shared__ __nv_bfloat16 Bh[32][40],  Bl[32][40];
    const int t = threadIdx.x, wid = t >> 5, l = t & 31;
    const int lr = l & 15, lc = (l >> 4) << 3;
    const int row0 = blockIdx.x * 128;
    const int fb0  = blockIdx.y * 448;

    float acc[4][4];
    #pragma unroll
    for (int i = 0; i < 4; i++)
        #pragma unroll
        for (int j = 0; j < 4; j++) acc[i][j] = 0.f;

    const uint32_t a_ah = s2u(Ah), a_al = s2u(Al), a_bh = s2u(Bh), a_bl = s2u(Bl);

    for (int s = 0; s < 14; s++){
        const int fb = fb0 + s*32;
        // stage A (128 x 32 bf16, hi+lo)
        #pragma unroll
        for (int i = 0; i < 2; i++){
            int idx = t + i*256;
            int r = idx >> 2, c4 = idx & 3;
            *(uint4*)&Ah[r][c4*8] = *(const uint4*)(g_xh + (size_t)(row0+r)*NF + fb + c4*8);
            *(uint4*)&Al[r][c4*8] = *(const uint4*)(g_xl + (size_t)(row0+r)*NF + fb + c4*8);
        }
        // stage B: Wt chunk [32][32] fp32 -> bf16 hi/lo
        {
            int r = t >> 3, c4 = t & 7;
            float4 wv = *(const float4*)(Wt + (size_t)(fb+r)*NU + c4*4);
            __nv_bfloat16 h[4], lo[4];
            split_bf16(wv.x, h[0], lo[0]); split_bf16(wv.y, h[1], lo[1]);
            split_bf16(wv.z, h[2], lo[2]); split_bf16(wv.w, h[3], lo[3]);
            *(uint2*)&Bh[r][c4*4] = *(uint2*)h;
            *(uint2*)&Bl[r][c4*4] = *(uint2*)lo;
        }
        __syncthreads();
        #pragma unroll
        for (int ks = 0; ks < 32; ks += 16){
            uint32_t fah[4], fal[4];
            ldsm4(fah, a_ah + ((wid*16 + lr)*40 + ks + lc)*2);
            ldsm4(fal, a_al + ((wid*16 + lr)*40 + ks + lc)*2);
            uint32_t fbh[8], fbl[8];
            ldsm4t(fbh + 0, a_bh + ((ks + lr)*40 + 0  + lc)*2);
            ldsm4t(fbh + 4, a_bh + ((ks + lr)*40 + 16 + lc)*2);
            ldsm4t(fbl + 0, a_bl + ((ks + lr)*40 + 0  + lc)*2);
            ldsm4t(fbl + 4, a_bl + ((ks + lr)*40 + 16 + lc)*2);
            #pragma unroll
            for (int ng = 0; ng < 4; ng++){
                mma_bf16(acc[ng], fah, fbh[ng*2], fbh[ng*2+1]);
                mma_bf16(acc[ng], fah, fbl[ng*2], fbl[ng*2+1]);
                mma_bf16(acc[ng], fal, fbh[ng*2], fbh[ng*2+1]);
            }
        }
        __syncthreads();
    }
    // store partials: g_pp[by][row][u]
    float* pp = g_pp + (size_t)blockIdx.y*NB*NL*NU;
    const int r0 = row0 + wid*16 + (l >> 2);
    const int c0 = (l & 3)*2;
    #pragma unroll
    for (int ng = 0; ng < 4; ng++){
        *(float2*)&pp[(size_t)r0*NU + ng*8 + c0]       = make_float2(acc[ng][0], acc[ng][1]);
        *(float2*)&pp[(size_t)(r0+8)*NU + ng*8 + c0]   = make_float2(acc[ng][2], acc[ng][3]);
    }
}

// ---------------------------------------------------------------------------
// K_pred: reduce partials -> g_p
// ---------------------------------------------------------------------------
__global__ __launch_bounds__(256) void k_pred(){
    int i = blockIdx.x*256 + threadIdx.x;
    float s = 0.f;
    #pragma unroll
    for (int j = 0; j < KSPLIT; j++) s += g_pp[(size_t)j*NB*NL*NU + i];
    g_p[i] = s;
}

// ---------------------------------------------------------------------------
// K_attn: a[b,q,k] = softmax_k(sigmoid(Wa·tanh(p_q+p_k+bh)+ba)); emit bf16 hi/lo
// ---------------------------------------------------------------------------
__global__ __launch_bounds__(256) void k_attn(const float* __restrict__ bh,
                                              const float* __restrict__ Wa,
                                              const float* __restrict__ ba){
    __shared__ float ps[NL][33];
    __shared__ float pqb[32];
    __shared__ float was[32];
    __shared__ float red[8];
    __shared__ float s_inv_total;

    const int t = threadIdx.x;
    const int b = blockIdx.x >> 8;
    const int q = blockIdx.x & 255;
    const float* pb = g_p + b*NL*NU;

    #pragma unroll
    for (int i = 0; i < 32; i++){
        int idx = t + i*256;
        ps[idx >> 5][idx & 31] = pb[idx];
    }
    if (t < 32){
        was[t] = Wa[t];
        pqb[t] = pb[q*NU + t] + bh[t];
    }
    __syncthreads();

    float acc = 0.f;
    #pragma unroll
    for (int u = 0; u < 32; u++)
        acc = fmaf(was[u], tanh_approx(pqb[u] + ps[t][u]), acc);

    float alpha = acc + ba[0];
    float s = 1.f / (1.f + __expf(-alpha));
    float e = __expf(s);

    float wsum = e;
    #pragma unroll
    for (int o = 16; o > 0; o >>= 1) wsum += __shfl_xor_sync(0xffffffffu, wsum, o);
    if ((t & 31) == 0) red[t >> 5] = wsum;
    __syncthreads();
    if (t == 0){
        float tot = 0.f;
        #pragma unroll
        for (int i = 0; i < 8; i++) tot += red[i];
        s_inv_total = 1.f / tot;
    }
    __syncthreads();

    float av = e * s_inv_total;
    __nv_bfloat16 h, lo;
    split_bf16(av, h, lo);
    size_t o = (size_t)b*NL*NL + (size_t)q*NL + t;
    g_ah[o] = h;
    g_al[o] = lo;
}

// ---------------------------------------------------------------------------
// K_out: out[b,q,f] = sum_k a[b,q,k]*x[b,k,f]  (bf16 split HMMA, 3 terms)
// CTA: BM=128 (q), BN=64 (f), BK=32. 8 warps as 4(M)x2(N), warp tile 32x32.
// grid (98, 2, 8), 256 threads.
// ---------------------------------------------------------------------------
__global__ __launch_bounds__(256) void k_out(float* __restrict__ out){
    __shared__ __nv_bfloat16 Ah[128][40], Al[128][40];
    __shared__ __nv_bfloat16 Bh[32][72],  Bl[32][72];
    const int t = threadIdx.x, wid = t >> 5, l = t & 31;
    const int lr = l & 15, lc = (l >> 4) << 3;
    const int b  = blockIdx.z;
    const int q0 = blockIdx.y * 128;
    const int f0 = blockIdx.x * 64;
    const int warp_m = wid >> 1, warp_n = wid & 1;

    const __nv_bfloat16* gah = g_ah + ((size_t)b*NL + q0)*NL;
    const __nv_bfloat16* gal = g_al + ((size_t)b*NL + q0)*NL;
    const __nv_bfloat16* gxh = g_xh + (size_t)b*NL*NF + f0;
    const __nv_bfloat16* gxl = g_xl + (size_t)b*NL*NF + f0;

    float acc[2][4][4];
    #pragma unroll
    for (int i = 0; i < 2; i++)
        #pragma unroll
        for (int j = 0; j < 4; j++)
            #pragma unroll
            for (int k = 0; k < 4; k++) acc[i][j][k] = 0.f;

    const uint32_t a_ah = s2u(Ah), a_al = s2u(Al), a_bh = s2u(Bh), a_bl = s2u(Bl);

    for (int k0 = 0; k0 < NL; k0 += 32){
        // stage A (128 q x 32 k, hi+lo): 512 uint4 per array
        #pragma unroll
        for (int i = 0; i < 2; i++){
            int idx = t + i*256;
            int r = idx >> 2, c4 = idx & 3;
            *(uint4*)&Ah[r][c4*8] = *(const uint4*)(gah + (size_t)r*NL + k0 + c4*8);
            *(uint4*)&Al[r][c4*8] = *(const uint4*)(gal + (size_t)r*NL + k0 + c4*8);
        }
        // stage B (32 k x 64 f, hi+lo): 256 uint4 per array
        {
            int r = t >> 3, c = (t & 7)*8;
            *(uint4*)&Bh[r][c] = *(const uint4*)(gxh + (size_t)(k0+r)*NF + c);
            *(uint4*)&Bl[r][c] = *(const uint4*)(gxl + (size_t)(k0+r)*NF + c);
        }
        __syncthreads();
        #pragma unroll
        for (int ks = 0; ks < 32; ks += 16){
            uint32_t fah[2][4], fal[2][4];
            #pragma unroll
            for (int mt = 0; mt < 2; mt++){
                ldsm4(fah[mt], a_ah + ((warp_m*32 + mt*16 + lr)*40 + ks + lc)*2);
                ldsm4(fal[mt], a_al + ((warp_m*32 + mt*16 + lr)*40 + ks + lc)*2);
            }
            uint32_t fbh[8], fbl[8];
            ldsm4t(fbh + 0, a_bh + ((ks + lr)*72 + warp_n*32 + 0  + lc)*2);
            ldsm4t(fbh + 4, a_bh + ((ks + lr)*72 + warp_n*32 + 16 + lc)*2);
            ldsm4t(fbl + 0, a_bl + ((ks + lr)*72 + warp_n*32 + 0  + lc)*2);
            ldsm4t(fbl + 4, a_bl + ((ks + lr)*72 + warp_n*32 + 16 + lc)*2);
            #pragma unroll
            for (int mt = 0; mt < 2; mt++){
                #pragma unroll
                for (int ng = 0; ng < 4; ng++){
                    mma_bf16(acc[mt][ng], fah[mt], fbh[ng*2], fbh[ng*2+1]);
                    mma_bf16(acc[mt][ng], fah[mt], fbl[ng*2], fbl[ng*2+1]);
                    mma_bf16(acc[mt][ng], fal[mt], fbh[ng*2], fbh[ng*2+1]);
                }
            }
        }
        __syncthreads();
    }

    // epilogue
    const int c0 = (l & 3)*2;
    #pragma unroll
    for (int mt = 0; mt < 2; mt++){
        const int row = q0 + warp_m*32 + mt*16 + (l >> 2);
        #pragma unroll
        for (int ng = 0; ng < 4; ng++){
            const int col = f0 + warp_n*32 + ng*8 + c0;
            *(float2*)&out[((size_t)(b*NL + row))*NF + col] =
                make_float2(acc[mt][ng][0], acc[mt][ng][1]);
            *(float2*)&out[((size_t)(b*NL + row + 8))*NF + col] =
                make_float2(acc[mt][ng][2], acc[mt][ng][3]);
        }
    }
}

// ---------------------------------------------------------------------------
extern "C" void kernel_launch(void* const* d_in, const int* in_sizes, int n_in,
                              void* d_out, int out_size){
    const float* inp = (const float*)d_in[0];
    const float* Wt  = (const float*)d_in[1];
    const float* bh  = (const float*)d_in[2];
    const float* Wa  = (const float*)d_in[3];
    const float* ba  = (const float*)d_in[4];
    float* out = (float*)d_out;

    k_conv<<<(NB*NL*(size_t)NF)/4/256, 256>>>(inp);
    k_proj<<<dim3(16, KSPLIT), 256>>>(Wt);
    k_pred<<<NB*NL*NU/256, 256>>>();
    k_attn<<<NB*NL, 256>>>(bh, Wa, ba);
    k_out<<<dim3(NF/64, NL/128, NB), 256>>>(out);
}

// round 4
// speedup vs baseline: 2.6732x; 1.1732x over previous
#include <cuda_runtime.h>
#include <cuda_bf16.h>
#include <cstdint>

#define NB 8
#define NL 256
#define NF 6272
#define NU 32
#define KSPLIT 14

// Scratch (no cudaMalloc allowed)
__device__ float g_p[NB*NL*NU];                      // reduced projections
__device__ float g_pp[KSPLIT*NB*NL*NU];              // projection partials (deterministic)
__device__ __nv_bfloat16 g_ah[NB*NL*NL], g_al[NB*NL*NL];   // a hi/lo [b][q][k]

// ---------------------------------------------------------------------------
// helpers
// ---------------------------------------------------------------------------
__device__ __forceinline__ uint32_t s2u(const void* p){
    uint32_t a;
    asm("{ .reg .u64 t; cvta.to.shared.u64 t, %1; cvt.u32.u64 %0, t; }" : "=r"(a) : "l"(p));
    return a;
}
__device__ __forceinline__ float tanh_approx(float x){
    float y; asm("tanh.approx.f32 %0, %1;" : "=f"(y) : "f"(x)); return y;
}
__device__ __forceinline__ void ldsm4(uint32_t r[4], uint32_t a){
    asm volatile("ldmatrix.sync.aligned.m8n8.x4.shared.b16 {%0,%1,%2,%3}, [%4];"
                 : "=r"(r[0]), "=r"(r[1]), "=r"(r[2]), "=r"(r[3]) : "r"(a));
}
__device__ __forceinline__ void ldsm4t(uint32_t r[4], uint32_t a){
    asm volatile("ldmatrix.sync.aligned.m8n8.x4.trans.shared.b16 {%0,%1,%2,%3}, [%4];"
                 : "=r"(r[0]), "=r"(r[1]), "=r"(r[2]), "=r"(r[3]) : "r"(a));
}
__device__ __forceinline__ void mma_bf16(float c[4], const uint32_t a[4], uint32_t b0, uint32_t b1){
    asm volatile(
        "mma.sync.aligned.m16n8k16.row.col.f32.bf16.bf16.f32 "
        "{%0,%1,%2,%3}, {%4,%5,%6,%7}, {%8,%9}, {%0,%1,%2,%3};"
        : "+f"(c[0]), "+f"(c[1]), "+f"(c[2]), "+f"(c[3])
        : "r"(a[0]), "r"(a[1]), "r"(a[2]), "r"(a[3]), "r"(b0), "r"(b1));
}
__device__ __forceinline__ void split_bf16(float v, __nv_bfloat16& h, __nv_bfloat16& l){
    h = __float2bfloat16(v);
    l = __float2bfloat16(v - __bfloat162float(h));
}
__device__ __forceinline__ void split4(float4 v, uint2& h, uint2& l){
    __nv_bfloat16 hh[4], ll[4];
    split_bf16(v.x, hh[0], ll[0]); split_bf16(v.y, hh[1], ll[1]);
    split_bf16(v.z, hh[2], ll[2]); split_bf16(v.w, hh[3], ll[3]);
    h = *(uint2*)hh; l = *(uint2*)ll;
}

// ---------------------------------------------------------------------------
// K_proj: p_partial[by] = x[rows, fchunk] @ Wt[fchunk, 32]  (bf16 split HMMA)
// grid (16, 14), 256 threads. Converts fp32 inputs -> hi/lo inline.
// Single smem buffer + register prefetch.
// ---------------------------------------------------------------------------
__global__ __launch_bounds__(256) void k_proj(const float* __restrict__ inp,
                                              const float* __restrict__ Wt){
    __shared__ __nv_bfloat16 Ah[128][40], Al[128][40];
    __shared__ __nv_bfloat16 Bh[32][40],  Bl[32][40];
    const int t = threadIdx.x, wid = t >> 5, l = t & 31;
    const int lr = l & 15, lc = (l >> 4) << 3;
    const int row0 = blockIdx.x * 128;
    const int fb0  = blockIdx.y * 448;

    // per-thread staging coords
    const int arR[4] = { (t+0)>>3, (t+256)>>3, (t+512)>>3, (t+768)>>3 };
    const int arC    = (t & 7)*4;          // same low bits for all i
    const int wrR    = t >> 3, wrC = (t & 7)*4;

    float acc[4][4];
    #pragma unroll
    for (int i = 0; i < 4; i++)
        #pragma unroll
        for (int j = 0; j < 4; j++) acc[i][j] = 0.f;

    const uint32_t a_ah = s2u(Ah), a_al = s2u(Al), a_bh = s2u(Bh), a_bl = s2u(Bl);

    float4 xv[4], wv;
    // prefetch s=0
    #pragma unroll
    for (int i = 0; i < 4; i++)
        xv[i] = *(const float4*)(inp + (size_t)(row0 + arR[i])*NF + fb0 + arC);
    wv = *(const float4*)(Wt + (size_t)(fb0 + wrR)*NU + wrC);

    for (int s = 0; s < 14; s++){
        // store prefetched regs -> smem (with split)
        #pragma unroll
        for (int i = 0; i < 4; i++){
            uint2 h, lo; split4(xv[i], h, lo);
            *(uint2*)&Ah[arR[i]][arC] = h;
            *(uint2*)&Al[arR[i]][arC] = lo;
        }
        {
            uint2 h, lo; split4(wv, h, lo);
            *(uint2*)&Bh[wrR][wrC] = h;
            *(uint2*)&Bl[wrR][wrC] = lo;
        }
        __syncthreads();

        if (s < 13){
            const int fb = fb0 + (s+1)*32;
            #pragma unroll
            for (int i = 0; i < 4; i++)
                xv[i] = *(const float4*)(inp + (size_t)(row0 + arR[i])*NF + fb + arC);
            wv = *(const float4*)(Wt + (size_t)(fb + wrR)*NU + wrC);
        }

        #pragma unroll
        for (int ks = 0; ks < 32; ks += 16){
            uint32_t fah[4], fal[4];
            ldsm4(fah, a_ah + ((wid*16 + lr)*40 + ks + lc)*2);
            ldsm4(fal, a_al + ((wid*16 + lr)*40 + ks + lc)*2);
            uint32_t fbh[8], fbl[8];
            ldsm4t(fbh + 0, a_bh + ((ks + lr)*40 + 0  + lc)*2);
            ldsm4t(fbh + 4, a_bh + ((ks + lr)*40 + 16 + lc)*2);
            ldsm4t(fbl + 0, a_bl + ((ks + lr)*40 + 0  + lc)*2);
            ldsm4t(fbl + 4, a_bl + ((ks + lr)*40 + 16 + lc)*2);
            #pragma unroll
            for (int ng = 0; ng < 4; ng++){
                mma_bf16(acc[ng], fah, fbh[ng*2], fbh[ng*2+1]);
                mma_bf16(acc[ng], fah, fbl[ng*2], fbl[ng*2+1]);
                mma_bf16(acc[ng], fal, fbh[ng*2], fbh[ng*2+1]);
            }
        }
        __syncthreads();
    }
    float* pp = g_pp + (size_t)blockIdx.y*NB*NL*NU;
    const int r0 = row0 + wid*16 + (l >> 2);
    const int c0 = (l & 3)*2;
    #pragma unroll
    for (int ng = 0; ng < 4; ng++){
        *(float2*)&pp[(size_t)r0*NU + ng*8 + c0]     = make_float2(acc[ng][0], acc[ng][1]);
        *(float2*)&pp[(size_t)(r0+8)*NU + ng*8 + c0] = make_float2(acc[ng][2], acc[ng][3]);
    }
}

// ---------------------------------------------------------------------------
// K_pred: reduce partials -> g_p
// ---------------------------------------------------------------------------
__global__ __launch_bounds__(256) void k_pred(){
    int i = blockIdx.x*256 + threadIdx.x;
    float s = 0.f;
    #pragma unroll
    for (int j = 0; j < KSPLIT; j++) s += g_pp[(size_t)j*NB*NL*NU + i];
    g_p[i] = s;
}

// ---------------------------------------------------------------------------
// K_attn: block handles (b, 8 queries). grid (32, 8), 256 threads (t = k).
// ---------------------------------------------------------------------------
__global__ __launch_bounds__(256) void k_attn(const float* __restrict__ bh,
                                              const float* __restrict__ Wa,
                                              const float* __restrict__ ba){
    __shared__ float ps[NL][33];
    __shared__ float pqb[8][32];
    __shared__ float was[32];
    __shared__ float red[8][8];    // [warp][j]
    __shared__ float inv[8];

    const int t = threadIdx.x;
    const int b = blockIdx.y;
    const int q0 = blockIdx.x * 8;
    const float* pb = g_p + b*NL*NU;
    const float ba0 = ba[0];

    #pragma unroll
    for (int i = 0; i < 32; i++){
        int idx = t + i*256;
        ps[idx >> 5][idx & 31] = pb[idx];
    }
    if (t < 32) was[t] = Wa[t];
    {
        int j = t >> 5, u = t & 31;
        pqb[j][u] = pb[(q0 + j)*NU + u] + bh[u];
    }
    __syncthreads();

    float e[8];
    #pragma unroll
    for (int j = 0; j < 8; j++){
        float acc = 0.f;
        #pragma unroll
        for (int u = 0; u < 32; u++)
            acc = fmaf(was[u], tanh_approx(pqb[j][u] + ps[t][u]), acc);
        float alpha = acc + ba0;
        float sg = 1.f / (1.f + __expf(-alpha));
        e[j] = __expf(sg);
    }

    // 8 block reductions
    #pragma unroll
    for (int j = 0; j < 8; j++){
        float w = e[j];
        #pragma unroll
        for (int o = 16; o > 0; o >>= 1) w += __shfl_xor_sync(0xffffffffu, w, o);
        if ((t & 31) == 0) red[t >> 5][j] = w;
    }
    __syncthreads();
    if (t < 8){
        float tot = 0.f;
        #pragma unroll
        for (int w = 0; w < 8; w++) tot += red[w][t];
        inv[t] = 1.f / tot;
    }
    __syncthreads();

    #pragma unroll
    for (int j = 0; j < 8; j++){
        float av = e[j] * inv[j];
        __nv_bfloat16 h, lo;
        split_bf16(av, h, lo);
        size_t o = (size_t)b*NL*NL + (size_t)(q0 + j)*NL + t;
        g_ah[o] = h;
        g_al[o] = lo;
    }
}

// ---------------------------------------------------------------------------
// K_out: out[b,q,f] = sum_k a[b,q,k]*x[b,k,f]  (bf16 split HMMA, 3 terms)
// BM=128, BN=64, BK=32; 8 warps 4(M)x2(N); double-buffered dynamic smem;
// B (inputs) converted fp32->hi/lo inline. grid (98, 2, 8), 256 threads.
// ---------------------------------------------------------------------------
// stage layout (bytes): Ah 128*40*2=10240 | Al 10240 | Bh 32*72*2=4608 | Bl 4608
#define STG   29696
#define OFF_AL 10240
#define OFF_BH 20480
#define OFF_BL 25088
#define K3_SMEM (2*STG)

__global__ __launch_bounds__(256) void k_out(const float* __restrict__ inp,
                                             float* __restrict__ out){
    extern __shared__ char sm[];
    const uint32_t smb = s2u(sm);
    const int t = threadIdx.x, wid = t >> 5, l = t & 31;
    const int lr = l & 15, lc = (l >> 4) << 3;
    const int b  = blockIdx.z;
    const int q0 = blockIdx.y * 128;
    const int f0 = blockIdx.x * 64;
    const int warp_m = wid >> 1, warp_n = wid & 1;

    const __nv_bfloat16* gah = g_ah + ((size_t)b*NL + q0)*NL;
    const __nv_bfloat16* gal = g_al + ((size_t)b*NL + q0)*NL;
    const float* gx = inp + (size_t)b*NL*NF + f0;

    // staging coords
    const int aR[2] = { (t+0)>>2, (t+256)>>2 };       // A rows (0..127)
    const int aC    = (t & 3)*8;                      // A col chunk (8 bf16)
    const int bR[2] = { (t+0)>>4, (t+256)>>4 };       // B rows (0..31)
    const int bC    = (t & 15)*4;                     // B col chunk (4 floats)

    float acc[2][4][4];
    #pragma unroll
    for (int i = 0; i < 2; i++)
        #pragma unroll
        for (int j = 0; j < 4; j++)
            #pragma unroll
            for (int k = 0; k < 4; k++) acc[i][j][k] = 0.f;

    uint4 avh[2], avl[2];
    float4 bv[2];

    // prologue: load chunk 0, store to stage 0
    #pragma unroll
    for (int i = 0; i < 2; i++){
        avh[i] = *(const uint4*)(gah + (size_t)aR[i]*NL + aC);
        avl[i] = *(const uint4*)(gal + (size_t)aR[i]*NL + aC);
        bv[i]  = *(const float4*)(gx + (size_t)bR[i]*NF + bC);
    }
    {
        char* s0 = sm;
        #pragma unroll
        for (int i = 0; i < 2; i++){
            *(uint4*)(s0 + (size_t)aR[i]*80 + aC*2)           = avh[i];
            *(uint4*)(s0 + OFF_AL + (size_t)aR[i]*80 + aC*2)  = avl[i];
            uint2 h, lo; split4(bv[i], h, lo);
            *(uint2*)(s0 + OFF_BH + (size_t)bR[i]*144 + bC*2) = h;
            *(uint2*)(s0 + OFF_BL + (size_t)bR[i]*144 + bC*2) = lo;
        }
    }
    __syncthreads();

    for (int c = 0; c < 8; c++){
        const int cur = c & 1;
        const uint32_t base = smb + cur*STG;

        if (c < 7){
            const int k0 = (c+1)*32;
            #pragma unroll
            for (int i = 0; i < 2; i++){
                avh[i] = *(const uint4*)(gah + (size_t)aR[i]*NL + k0 + aC);
                avl[i] = *(const uint4*)(gal + (size_t)aR[i]*NL + k0 + aC);
                bv[i]  = *(const float4*)(gx + (size_t)(k0 + bR[i])*NF + bC);
            }
        }

        #pragma unroll
        for (int ks = 0; ks < 32; ks += 16){
            uint32_t fah[2][4], fal[2][4];
            #pragma unroll
            for (int mt = 0; mt < 2; mt++){
                ldsm4(fah[mt], base + ((warp_m*32 + mt*16 + lr)*40 + ks + lc)*2);
                ldsm4(fal[mt], base + OFF_AL + ((warp_m*32 + mt*16 + lr)*40 + ks + lc)*2);
            }
            uint32_t fbh[8], fbl[8];
            ldsm4t(fbh + 0, base + OFF_BH + ((ks + lr)*72 + warp_n*32 + 0  + lc)*2);
            ldsm4t(fbh + 4, base + OFF_BH + ((ks + lr)*72 + warp_n*32 + 16 + lc)*2);
            ldsm4t(fbl + 0, base + OFF_BL + ((ks + lr)*72 + warp_n*32 + 0  + lc)*2);
            ldsm4t(fbl + 4, base + OFF_BL + ((ks + lr)*72 + warp_n*32 + 16 + lc)*2);
            #pragma unroll
            for (int mt = 0; mt < 2; mt++){
                #pragma unroll
                for (int ng = 0; ng < 4; ng++){
                    mma_bf16(acc[mt][ng], fah[mt], fbh[ng*2], fbh[ng*2+1]);
                    mma_bf16(acc[mt][ng], fah[mt], fbl[ng*2], fbl[ng*2+1]);
                    mma_bf16(acc[mt][ng], fal[mt], fbh[ng*2], fbh[ng*2+1]);
                }
            }
        }

        if (c < 7){
            char* sn = sm + (1 - cur)*STG;
            #pragma unroll
            for (int i = 0; i < 2; i++){
                *(uint4*)(sn + (size_t)aR[i]*80 + aC*2)           = avh[i];
                *(uint4*)(sn + OFF_AL + (size_t)aR[i]*80 + aC*2)  = avl[i];
                uint2 h, lo; split4(bv[i], h, lo);
                *(uint2*)(sn + OFF_BH + (size_t)bR[i]*144 + bC*2) = h;
                *(uint2*)(sn + OFF_BL + (size_t)bR[i]*144 + bC*2) = lo;
            }
        }
        __syncthreads();
    }

    // epilogue
    const int c0 = (l & 3)*2;
    #pragma unroll
    for (int mt = 0; mt < 2; mt++){
        const int row = q0 + warp_m*32 + mt*16 + (l >> 2);
        #pragma unroll
        for (int ng = 0; ng < 4; ng++){
            const int col = f0 + warp_n*32 + ng*8 + c0;
            *(float2*)&out[((size_t)(b*NL + row))*NF + col] =
                make_float2(acc[mt][ng][0], acc[mt][ng][1]);
            *(float2*)&out[((size_t)(b*NL + row + 8))*NF + col] =
                make_float2(acc[mt][ng][2], acc[mt][ng][3]);
        }
    }
}

// ---------------------------------------------------------------------------
extern "C" void kernel_launch(void* const* d_in, const int* in_sizes, int n_in,
                              void* d_out, int out_size){
    const float* inp = (const float*)d_in[0];
    const float* Wt  = (const float*)d_in[1];
    const float* bh  = (const float*)d_in[2];
    const float* Wa  = (const float*)d_in[3];
    const float* ba  = (const float*)d_in[4];
    float* out = (float*)d_out;

    static bool attr_set = false;
    if (!attr_set){
        cudaFuncSetAttribute(k_out, cudaFuncAttributeMaxDynamicSharedMemorySize, K3_SMEM);
        attr_set = true;
    }

    k_proj<<<dim3(16, KSPLIT), 256>>>(inp, Wt);
    k_pred<<<NB*NL*NU/256, 256>>>();
    k_attn<<<dim3(NL/8, NB), 256>>>(bh, Wa, ba);
    k_out<<<dim3(NF/64, NL/128, NB), 256, K3_SMEM>>>(inp, out);
}

// round 5
// speedup vs baseline: 2.8207x; 1.0552x over previous
#include <cuda_runtime.h>
#include <cuda_bf16.h>
#include <cstdint>

#define NB 8
#define NL 256
#define NF 6272
#define NU 32
#define KSPLIT 14

// Scratch (no cudaMalloc allowed)
__device__ float g_p[NB*NL*NU];                      // reduced projections
__device__ float g_pp[KSPLIT*NB*NL*NU];              // projection partials (deterministic)
__device__ __nv_bfloat16 g_ah[NB*NL*NL], g_al[NB*NL*NL];   // a hi/lo [b][q][k]

// ---------------------------------------------------------------------------
// helpers
// ---------------------------------------------------------------------------
__device__ __forceinline__ uint32_t s2u(const void* p){
    uint32_t a;
    asm("{ .reg .u64 t; cvta.to.shared.u64 t, %1; cvt.u32.u64 %0, t; }" : "=r"(a) : "l"(p));
    return a;
}
__device__ __forceinline__ float tanh_approx(float x){
    float y; asm("tanh.approx.f32 %0, %1;" : "=f"(y) : "f"(x)); return y;
}
__device__ __forceinline__ void ldsm4(uint32_t r[4], uint32_t a){
    asm volatile("ldmatrix.sync.aligned.m8n8.x4.shared.b16 {%0,%1,%2,%3}, [%4];"
                 : "=r"(r[0]), "=r"(r[1]), "=r"(r[2]), "=r"(r[3]) : "r"(a));
}
__device__ __forceinline__ void ldsm4t(uint32_t r[4], uint32_t a){
    asm volatile("ldmatrix.sync.aligned.m8n8.x4.trans.shared.b16 {%0,%1,%2,%3}, [%4];"
                 : "=r"(r[0]), "=r"(r[1]), "=r"(r[2]), "=r"(r[3]) : "r"(a));
}
__device__ __forceinline__ void mma_bf16(float c[4], const uint32_t a[4], uint32_t b0, uint32_t b1){
    asm volatile(
        "mma.sync.aligned.m16n8k16.row.col.f32.bf16.bf16.f32 "
        "{%0,%1,%2,%3}, {%4,%5,%6,%7}, {%8,%9}, {%0,%1,%2,%3};"
        : "+f"(c[0]), "+f"(c[1]), "+f"(c[2]), "+f"(c[3])
        : "r"(a[0]), "r"(a[1]), "r"(a[2]), "r"(a[3]), "r"(b0), "r"(b1));
}
__device__ __forceinline__ void split_bf16(float v, __nv_bfloat16& h, __nv_bfloat16& l){
    h = __float2bfloat16(v);
    l = __float2bfloat16(v - __bfloat162float(h));
}
__device__ __forceinline__ void split4(float4 v, uint2& h, uint2& l){
    __nv_bfloat16 hh[4], ll[4];
    split_bf16(v.x, hh[0], ll[0]); split_bf16(v.y, hh[1], ll[1]);
    split_bf16(v.z, hh[2], ll[2]); split_bf16(v.w, hh[3], ll[3]);
    h = *(uint2*)hh; l = *(uint2*)ll;
}
__device__ __forceinline__ void cp16(uint32_t dst, const void* src){
    asm volatile("cp.async.ca.shared.global [%0], [%1], 16;" :: "r"(dst), "l"(src));
}
__device__ __forceinline__ void cp_commit(){ asm volatile("cp.async.commit_group;"); }
__device__ __forceinline__ void cp_wait0(){ asm volatile("cp.async.wait_group 0;"); }

// ---------------------------------------------------------------------------
// K_proj: p_partial[by] = x[rows, fchunk] @ Wt[fchunk, 32]  (bf16 split HMMA)
// grid (16, 14), 256 threads. Converts fp32 inputs -> hi/lo inline.
// ---------------------------------------------------------------------------
__global__ __launch_bounds__(256) void k_proj(const float* __restrict__ inp,
                                              const float* __restrict__ Wt){
    __shared__ __nv_bfloat16 Ah[128][40], Al[128][40];
    __shared__ __nv_bfloat16 Bh[32][40],  Bl[32][40];
    const int t = threadIdx.x, wid = t >> 5, l = t & 31;
    const int lr = l & 15, lc = (l >> 4) << 3;
    const int row0 = blockIdx.x * 128;
    const int fb0  = blockIdx.y * 448;

    const int arR[4] = { (t+0)>>3, (t+256)>>3, (t+512)>>3, (t+768)>>3 };
    const int arC    = (t & 7)*4;
    const int wrR    = t >> 3, wrC = (t & 7)*4;

    float acc[4][4];
    #pragma unroll
    for (int i = 0; i < 4; i++)
        #pragma unroll
        for (int j = 0; j < 4; j++) acc[i][j] = 0.f;

    const uint32_t a_ah = s2u(Ah), a_al = s2u(Al), a_bh = s2u(Bh), a_bl = s2u(Bl);

    float4 xv[4], wv;
    #pragma unroll
    for (int i = 0; i < 4; i++)
        xv[i] = *(const float4*)(inp + (size_t)(row0 + arR[i])*NF + fb0 + arC);
    wv = *(const float4*)(Wt + (size_t)(fb0 + wrR)*NU + wrC);

    for (int s = 0; s < 14; s++){
        #pragma unroll
        for (int i = 0; i < 4; i++){
            uint2 h, lo; split4(xv[i], h, lo);
            *(uint2*)&Ah[arR[i]][arC] = h;
            *(uint2*)&Al[arR[i]][arC] = lo;
        }
        {
            uint2 h, lo; split4(wv, h, lo);
            *(uint2*)&Bh[wrR][wrC] = h;
            *(uint2*)&Bl[wrR][wrC] = lo;
        }
        __syncthreads();

        if (s < 13){
            const int fb = fb0 + (s+1)*32;
            #pragma unroll
            for (int i = 0; i < 4; i++)
                xv[i] = *(const float4*)(inp + (size_t)(row0 + arR[i])*NF + fb + arC);
            wv = *(const float4*)(Wt + (size_t)(fb + wrR)*NU + wrC);
        }

        #pragma unroll
        for (int ks = 0; ks < 32; ks += 16){
            uint32_t fah[4], fal[4];
            ldsm4(fah, a_ah + ((wid*16 + lr)*40 + ks + lc)*2);
            ldsm4(fal, a_al + ((wid*16 + lr)*40 + ks + lc)*2);
            uint32_t fbh[8], fbl[8];
            ldsm4t(fbh + 0, a_bh + ((ks + lr)*40 + 0  + lc)*2);
            ldsm4t(fbh + 4, a_bh + ((ks + lr)*40 + 16 + lc)*2);
            ldsm4t(fbl + 0, a_bl + ((ks + lr)*40 + 0  + lc)*2);
            ldsm4t(fbl + 4, a_bl + ((ks + lr)*40 + 16 + lc)*2);
            #pragma unroll
            for (int ng = 0; ng < 4; ng++){
                mma_bf16(acc[ng], fah, fbh[ng*2], fbh[ng*2+1]);
                mma_bf16(acc[ng], fah, fbl[ng*2], fbl[ng*2+1]);
                mma_bf16(acc[ng], fal, fbh[ng*2], fbh[ng*2+1]);
            }
        }
        __syncthreads();
    }
    float* pp = g_pp + (size_t)blockIdx.y*NB*NL*NU;
    const int r0 = row0 + wid*16 + (l >> 2);
    const int c0 = (l & 3)*2;
    #pragma unroll
    for (int ng = 0; ng < 4; ng++){
        *(float2*)&pp[(size_t)r0*NU + ng*8 + c0]     = make_float2(acc[ng][0], acc[ng][1]);
        *(float2*)&pp[(size_t)(r0+8)*NU + ng*8 + c0] = make_float2(acc[ng][2], acc[ng][3]);
    }
}

// ---------------------------------------------------------------------------
// K_pred: reduce partials -> g_p
// ---------------------------------------------------------------------------
__global__ __launch_bounds__(256) void k_pred(){
    int i = blockIdx.x*256 + threadIdx.x;
    float s = 0.f;
    #pragma unroll
    for (int j = 0; j < KSPLIT; j++) s += g_pp[(size_t)j*NB*NL*NU + i];
    g_p[i] = s;
}

// ---------------------------------------------------------------------------
// K_attn: block handles (b, 8 queries). grid (32, 8), 256 threads (t = k).
// ---------------------------------------------------------------------------
__global__ __launch_bounds__(256) void k_attn(const float* __restrict__ bh,
                                              const float* __restrict__ Wa,
                                              const float* __restrict__ ba){
    __shared__ float ps[NL][33];
    __shared__ float pqb[8][32];
    __shared__ float was[32];
    __shared__ float red[8][8];
    __shared__ float inv[8];

    const int t = threadIdx.x;
    const int b = blockIdx.y;
    const int q0 = blockIdx.x * 8;
    const float* pb = g_p + b*NL*NU;
    const float ba0 = ba[0];

    #pragma unroll
    for (int i = 0; i < 32; i++){
        int idx = t + i*256;
        ps[idx >> 5][idx & 31] = pb[idx];
    }
    if (t < 32) was[t] = Wa[t];
    {
        int j = t >> 5, u = t & 31;
        pqb[j][u] = pb[(q0 + j)*NU + u] + bh[u];
    }
    __syncthreads();

    float e[8];
    #pragma unroll
    for (int j = 0; j < 8; j++){
        float acc = 0.f;
        #pragma unroll
        for (int u = 0; u < 32; u++)
            acc = fmaf(was[u], tanh_approx(pqb[j][u] + ps[t][u]), acc);
        float alpha = acc + ba0;
        float sg = 1.f / (1.f + __expf(-alpha));
        e[j] = __expf(sg);
    }

    #pragma unroll
    for (int j = 0; j < 8; j++){
        float w = e[j];
        #pragma unroll
        for (int o = 16; o > 0; o >>= 1) w += __shfl_xor_sync(0xffffffffu, w, o);
        if ((t & 31) == 0) red[t >> 5][j] = w;
    }
    __syncthreads();
    if (t < 8){
        float tot = 0.f;
        #pragma unroll
        for (int w = 0; w < 8; w++) tot += red[w][t];
        inv[t] = 1.f / tot;
    }
    __syncthreads();

    #pragma unroll
    for (int j = 0; j < 8; j++){
        float av = e[j] * inv[j];
        __nv_bfloat16 h, lo;
        split_bf16(av, h, lo);
        size_t o = (size_t)b*NL*NL + (size_t)(q0 + j)*NL + t;
        g_ah[o] = h;
        g_al[o] = lo;
    }
}

// ---------------------------------------------------------------------------
// K_out: out[b,q,f] = sum_k a[b,q,k]*x[b,k,f]  (bf16 split HMMA, 3 terms)
// BM=128, BN=128, BK=32; 8 warps 2(M)x4(N), warp tile 64x32 (mt=4, ng=4).
// A tiles via cp.async (bf16 in gmem); B converted fp32->hi/lo in regs.
// Double-buffered. grid (49, 2, 8), 256 threads.
// ---------------------------------------------------------------------------
// stage layout (bytes): Ah 128*40*2=10240 | Al 10240 | Bh 32*136*2=8704 | Bl 8704
#define STG    37888
#define OFF_AL 10240
#define OFF_BH 20480
#define OFF_BL 29184
#define K3_SMEM (2*STG)

__global__ __launch_bounds__(256, 2) void k_out(const float* __restrict__ inp,
                                                float* __restrict__ out){
    extern __shared__ char sm[];
    const uint32_t smb = s2u(sm);
    const int t = threadIdx.x, wid = t >> 5, l = t & 31;
    const int lr = l & 15, lc = (l >> 4) << 3;
    const int b  = blockIdx.z;
    const int q0 = blockIdx.y * 128;
    const int f0 = blockIdx.x * 128;
    const int warp_m = wid >> 2, warp_n = wid & 3;   // 2 x 4

    const __nv_bfloat16* gah = g_ah + ((size_t)b*NL + q0)*NL;
    const __nv_bfloat16* gal = g_al + ((size_t)b*NL + q0)*NL;
    const float* gx = inp + (size_t)b*NL*NF + f0;

    // A staging coords (cp.async 16B): 512 uint4 per array -> 2 per thread
    const int aR[2] = { (t+0)>>2, (t+256)>>2 };
    const int aC    = (t & 3)*8;                     // 8 bf16 = 16B
    // B staging coords: 32 rows x 128 floats = 1024 float4 -> 4 per thread
    int bR[4], bC = 0;
    #pragma unroll
    for (int i = 0; i < 4; i++) bR[i] = (t + i*256) >> 5;
    bC = (t & 31)*4;

    float acc[4][4][4];
    #pragma unroll
    for (int mt = 0; mt < 4; mt++)
        #pragma unroll
        for (int ng = 0; ng < 4; ng++)
            #pragma unroll
            for (int k = 0; k < 4; k++) acc[mt][ng][k] = 0.f;

    float4 bv[4];

    // ---- prologue: chunk 0 -> stage 0
    {
        const uint32_t s0 = smb;
        #pragma unroll
        for (int i = 0; i < 2; i++){
            cp16(s0 + (uint32_t)aR[i]*80 + aC*2,           gah + (size_t)aR[i]*NL + aC);
            cp16(s0 + OFF_AL + (uint32_t)aR[i]*80 + aC*2,  gal + (size_t)aR[i]*NL + aC);
        }
        cp_commit();
        #pragma unroll
        for (int i = 0; i < 4; i++)
            bv[i] = *(const float4*)(gx + (size_t)bR[i]*NF + bC);
        char* sp = sm;
        #pragma unroll
        for (int i = 0; i < 4; i++){
            uint2 h, lo; split4(bv[i], h, lo);
            *(uint2*)(sp + OFF_BH + (size_t)bR[i]*272 + bC*2) = h;
            *(uint2*)(sp + OFF_BL + (size_t)bR[i]*272 + bC*2) = lo;
        }
        cp_wait0();
    }
    __syncthreads();

    for (int c = 0; c < 8; c++){
        const int cur = c & 1;
        const uint32_t base = smb + cur*STG;

        if (c < 7){
            const int k0 = (c+1)*32;
            const uint32_t nxt = smb + (1-cur)*STG;
            #pragma unroll
            for (int i = 0; i < 2; i++){
                cp16(nxt + (uint32_t)aR[i]*80 + aC*2,          gah + (size_t)aR[i]*NL + k0 + aC);
                cp16(nxt + OFF_AL + (uint32_t)aR[i]*80 + aC*2, gal + (size_t)aR[i]*NL + k0 + aC);
            }
            cp_commit();
            #pragma unroll
            for (int i = 0; i < 4; i++)
                bv[i] = *(const float4*)(gx + (size_t)(k0 + bR[i])*NF + bC);
        }

        #pragma unroll
        for (int ks = 0; ks < 32; ks += 16){
            uint32_t fbh[8], fbl[8];
            ldsm4t(fbh + 0, base + OFF_BH + ((ks + lr)*136 + warp_n*32 + 0  + lc)*2);
            ldsm4t(fbh + 4, base + OFF_BH + ((ks + lr)*136 + warp_n*32 + 16 + lc)*2);
            ldsm4t(fbl + 0, base + OFF_BL + ((ks + lr)*136 + warp_n*32 + 0  + lc)*2);
            ldsm4t(fbl + 4, base + OFF_BL + ((ks + lr)*136 + warp_n*32 + 16 + lc)*2);
            #pragma unroll
            for (int mt = 0; mt < 4; mt++){
                uint32_t fah[4], fal[4];
                ldsm4(fah, base + ((warp_m*64 + mt*16 + lr)*40 + ks + lc)*2);
                ldsm4(fal, base + OFF_AL + ((warp_m*64 + mt*16 + lr)*40 + ks + lc)*2);
                #pragma unroll
                for (int ng = 0; ng < 4; ng++){
                    mma_bf16(acc[mt][ng], fah, fbh[ng*2], fbh[ng*2+1]);
                    mma_bf16(acc[mt][ng], fah, fbl[ng*2], fbl[ng*2+1]);
                    mma_bf16(acc[mt][ng], fal, fbh[ng*2], fbh[ng*2+1]);
                }
            }
        }

        if (c < 7){
            char* sn = sm + (1-cur)*STG;
            #pragma unroll
            for (int i = 0; i < 4; i++){
                uint2 h, lo; split4(bv[i], h, lo);
                *(uint2*)(sn + OFF_BH + (size_t)bR[i]*272 + bC*2) = h;
                *(uint2*)(sn + OFF_BL + (size_t)bR[i]*272 + bC*2) = lo;
            }
            cp_wait0();
        }
        __syncthreads();
    }

    // epilogue
    const int c0 = (l & 3)*2;
    #pragma unroll
    for (int mt = 0; mt < 4; mt++){
        const int row = q0 + warp_m*64 + mt*16 + (l >> 2);
        #pragma unroll
        for (int ng = 0; ng < 4; ng++){
            const int col = f0 + warp_n*32 + ng*8 + c0;
            *(float2*)&out[((size_t)(b*NL + row))*NF + col] =
                make_float2(acc[mt][ng][0], acc[mt][ng][1]);
            *(float2*)&out[((size_t)(b*NL + row + 8))*NF + col] =
                make_float2(acc[mt][ng][2], acc[mt][ng][3]);
        }
    }
}

// ---------------------------------------------------------------------------
extern "C" void kernel_launch(void* const* d_in, const int* in_sizes, int n_in,
                              void* d_out, int out_size){
    const float* inp = (const float*)d_in[0];
    const float* Wt  = (const float*)d_in[1];
    const float* bh  = (const float*)d_in[2];
    const float* Wa  = (const float*)d_in[3];
    const float* ba  = (const float*)d_in[4];
    float* out = (float*)d_out;

    static bool attr_set = false;
    if (!attr_set){
        cudaFuncSetAttribute(k_out, cudaFuncAttributeMaxDynamicSharedMemorySize, K3_SMEM);
        attr_set = true;
    }

    k_proj<<<dim3(16, KSPLIT), 256>>>(inp, Wt);
    k_pred<<<NB*NL*NU/256, 256>>>();
    k_attn<<<dim3(NL/8, NB), 256>>>(bh, Wa, ba);
    k_out<<<dim3(NF/128, NL/128, NB), 256, K3_SMEM>>>(inp, out);
}

// round 6
// speedup vs baseline: 3.4650x; 1.2284x over previous
#include <cuda_runtime.h>
#include <cuda_bf16.h>
#include <cuda_fp16.h>
#include <cstdint>

#define NB 8
#define NL 256
#define NF 6272
#define NU 32
#define KSPLIT 14

// Scratch (no cudaMalloc allowed)
__device__ float g_p[NB*NL*NU];                      // reduced projections
__device__ float g_pp[KSPLIT*NB*NL*NU];              // projection partials (deterministic)
__device__ __half g_af[NB*NL*NL];                    // a (softmax weights) fp16 [b][q][k]

// ---------------------------------------------------------------------------
// helpers
// ---------------------------------------------------------------------------
__device__ __forceinline__ uint32_t s2u(const void* p){
    uint32_t a;
    asm("{ .reg .u64 t; cvta.to.shared.u64 t, %1; cvt.u32.u64 %0, t; }" : "=r"(a) : "l"(p));
    return a;
}
__device__ __forceinline__ float tanh_approx(float x){
    float y; asm("tanh.approx.f32 %0, %1;" : "=f"(y) : "f"(x)); return y;
}
__device__ __forceinline__ void ldsm4(uint32_t r[4], uint32_t a){
    asm volatile("ldmatrix.sync.aligned.m8n8.x4.shared.b16 {%0,%1,%2,%3}, [%4];"
                 : "=r"(r[0]), "=r"(r[1]), "=r"(r[2]), "=r"(r[3]) : "r"(a));
}
__device__ __forceinline__ void ldsm4t(uint32_t r[4], uint32_t a){
    asm volatile("ldmatrix.sync.aligned.m8n8.x4.trans.shared.b16 {%0,%1,%2,%3}, [%4];"
                 : "=r"(r[0]), "=r"(r[1]), "=r"(r[2]), "=r"(r[3]) : "r"(a));
}
__device__ __forceinline__ void mma_bf16(float c[4], const uint32_t a[4], uint32_t b0, uint32_t b1){
    asm volatile(
        "mma.sync.aligned.m16n8k16.row.col.f32.bf16.bf16.f32 "
        "{%0,%1,%2,%3}, {%4,%5,%6,%7}, {%8,%9}, {%0,%1,%2,%3};"
        : "+f"(c[0]), "+f"(c[1]), "+f"(c[2]), "+f"(c[3])
        : "r"(a[0]), "r"(a[1]), "r"(a[2]), "r"(a[3]), "r"(b0), "r"(b1));
}
__device__ __forceinline__ void mma_f16(float c[4], const uint32_t a[4], uint32_t b0, uint32_t b1){
    asm volatile(
        "mma.sync.aligned.m16n8k16.row.col.f32.f16.f16.f32 "
        "{%0,%1,%2,%3}, {%4,%5,%6,%7}, {%8,%9}, {%0,%1,%2,%3};"
        : "+f"(c[0]), "+f"(c[1]), "+f"(c[2]), "+f"(c[3])
        : "r"(a[0]), "r"(a[1]), "r"(a[2]), "r"(a[3]), "r"(b0), "r"(b1));
}
__device__ __forceinline__ void split_bf16(float v, __nv_bfloat16& h, __nv_bfloat16& l){
    h = __float2bfloat16(v);
    l = __float2bfloat16(v - __bfloat162float(h));
}
__device__ __forceinline__ void split4(float4 v, uint2& h, uint2& l){
    __nv_bfloat16 hh[4], ll[4];
    split_bf16(v.x, hh[0], ll[0]); split_bf16(v.y, hh[1], ll[1]);
    split_bf16(v.z, hh[2], ll[2]); split_bf16(v.w, hh[3], ll[3]);
    h = *(uint2*)hh; l = *(uint2*)ll;
}
__device__ __forceinline__ void split4h(float4 v, uint2& h, uint2& l){
    __half hh[4], ll[4];
    hh[0] = __float2half(v.x); ll[0] = __float2half(v.x - __half2float(hh[0]));
    hh[1] = __float2half(v.y); ll[1] = __float2half(v.y - __half2float(hh[1]));
    hh[2] = __float2half(v.z); ll[2] = __float2half(v.z - __half2float(hh[2]));
    hh[3] = __float2half(v.w); ll[3] = __float2half(v.w - __half2float(hh[3]));
    h = *(uint2*)hh; l = *(uint2*)ll;
}
__device__ __forceinline__ void cp16(uint32_t dst, const void* src){
    asm volatile("cp.async.ca.shared.global [%0], [%1], 16;" :: "r"(dst), "l"(src));
}
__device__ __forceinline__ void cp_commit(){ asm volatile("cp.async.commit_group;"); }
__device__ __forceinline__ void cp_wait0(){ asm volatile("cp.async.wait_group 0;"); }

// ---------------------------------------------------------------------------
// K_proj: p_partial[by] = x[rows, fchunk] @ Wt[fchunk, 32]  (bf16 split HMMA)
// grid (16, 14), 256 threads. Converts fp32 inputs -> hi/lo inline.
// ---------------------------------------------------------------------------
__global__ __launch_bounds__(256) void k_proj(const float* __restrict__ inp,
                                              const float* __restrict__ Wt){
    __shared__ __nv_bfloat16 Ah[128][40], Al[128][40];
    __shared__ __nv_bfloat16 Bh[32][40],  Bl[32][40];
    const int t = threadIdx.x, wid = t >> 5, l = t & 31;
    const int lr = l & 15, lc = (l >> 4) << 3;
    const int row0 = blockIdx.x * 128;
    const int fb0  = blockIdx.y * 448;

    const int arR[4] = { (t+0)>>3, (t+256)>>3, (t+512)>>3, (t+768)>>3 };
    const int arC    = (t & 7)*4;
    const int wrR    = t >> 3, wrC = (t & 7)*4;

    float acc[4][4];
    #pragma unroll
    for (int i = 0; i < 4; i++)
        #pragma unroll
        for (int j = 0; j < 4; j++) acc[i][j] = 0.f;

    const uint32_t a_ah = s2u(Ah), a_al = s2u(Al), a_bh = s2u(Bh), a_bl = s2u(Bl);

    float4 xv[4], wv;
    #pragma unroll
    for (int i = 0; i < 4; i++)
        xv[i] = *(const float4*)(inp + (size_t)(row0 + arR[i])*NF + fb0 + arC);
    wv = *(const float4*)(Wt + (size_t)(fb0 + wrR)*NU + wrC);

    for (int s = 0; s < 14; s++){
        #pragma unroll
        for (int i = 0; i < 4; i++){
            uint2 h, lo; split4(xv[i], h, lo);
            *(uint2*)&Ah[arR[i]][arC] = h;
            *(uint2*)&Al[arR[i]][arC] = lo;
        }
        {
            uint2 h, lo; split4(wv, h, lo);
            *(uint2*)&Bh[wrR][wrC] = h;
            *(uint2*)&Bl[wrR][wrC] = lo;
        }
        __syncthreads();

        if (s < 13){
            const int fb = fb0 + (s+1)*32;
            #pragma unroll
            for (int i = 0; i < 4; i++)
                xv[i] = *(const float4*)(inp + (size_t)(row0 + arR[i])*NF + fb + arC);
            wv = *(const float4*)(Wt + (size_t)(fb + wrR)*NU + wrC);
        }

        #pragma unroll
        for (int ks = 0; ks < 32; ks += 16){
            uint32_t fah[4], fal[4];
            ldsm4(fah, a_ah + ((wid*16 + lr)*40 + ks + lc)*2);
            ldsm4(fal, a_al + ((wid*16 + lr)*40 + ks + lc)*2);
            uint32_t fbh[8], fbl[8];
            ldsm4t(fbh + 0, a_bh + ((ks + lr)*40 + 0  + lc)*2);
            ldsm4t(fbh + 4, a_bh + ((ks + lr)*40 + 16 + lc)*2);
            ldsm4t(fbl + 0, a_bl + ((ks + lr)*40 + 0  + lc)*2);
            ldsm4t(fbl + 4, a_bl + ((ks + lr)*40 + 16 + lc)*2);
            #pragma unroll
            for (int ng = 0; ng < 4; ng++){
                mma_bf16(acc[ng], fah, fbh[ng*2], fbh[ng*2+1]);
                mma_bf16(acc[ng], fah, fbl[ng*2], fbl[ng*2+1]);
                mma_bf16(acc[ng], fal, fbh[ng*2], fbh[ng*2+1]);
            }
        }
        __syncthreads();
    }
    float* pp = g_pp + (size_t)blockIdx.y*NB*NL*NU;
    const int r0 = row0 + wid*16 + (l >> 2);
    const int c0 = (l & 3)*2;
    #pragma unroll
    for (int ng = 0; ng < 4; ng++){
        *(float2*)&pp[(size_t)r0*NU + ng*8 + c0]     = make_float2(acc[ng][0], acc[ng][1]);
        *(float2*)&pp[(size_t)(r0+8)*NU + ng*8 + c0] = make_float2(acc[ng][2], acc[ng][3]);
    }
}

// ---------------------------------------------------------------------------
// K_pred: reduce partials -> g_p
// ---------------------------------------------------------------------------
__global__ __launch_bounds__(256) void k_pred(){
    int i = blockIdx.x*256 + threadIdx.x;
    float s = 0.f;
    #pragma unroll
    for (int j = 0; j < KSPLIT; j++) s += g_pp[(size_t)j*NB*NL*NU + i];
    g_p[i] = s;
}

// ---------------------------------------------------------------------------
// K_attn: block handles (b, 8 queries). grid (32, 8), 256 threads (t = k).
// Emits a in fp16.
// ---------------------------------------------------------------------------
__global__ __launch_bounds__(256) void k_attn(const float* __restrict__ bh,
                                              const float* __restrict__ Wa,
                                              const float* __restrict__ ba){
    __shared__ float ps[NL][33];
    __shared__ float pqb[8][32];
    __shared__ float was[32];
    __shared__ float red[8][8];
    __shared__ float inv[8];

    const int t = threadIdx.x;
    const int b = blockIdx.y;
    const int q0 = blockIdx.x * 8;
    const float* pb = g_p + b*NL*NU;
    const float ba0 = ba[0];

    #pragma unroll
    for (int i = 0; i < 32; i++){
        int idx = t + i*256;
        ps[idx >> 5][idx & 31] = pb[idx];
    }
    if (t < 32) was[t] = Wa[t];
    {
        int j = t >> 5, u = t & 31;
        pqb[j][u] = pb[(q0 + j)*NU + u] + bh[u];
    }
    __syncthreads();

    float e[8];
    #pragma unroll
    for (int j = 0; j < 8; j++){
        float acc = 0.f;
        #pragma unroll
        for (int u = 0; u < 32; u++)
            acc = fmaf(was[u], tanh_approx(pqb[j][u] + ps[t][u]), acc);
        float alpha = acc + ba0;
        float sg = 1.f / (1.f + __expf(-alpha));
        e[j] = __expf(sg);
    }

    #pragma unroll
    for (int j = 0; j < 8; j++){
        float w = e[j];
        #pragma unroll
        for (int o = 16; o > 0; o >>= 1) w += __shfl_xor_sync(0xffffffffu, w, o);
        if ((t & 31) == 0) red[t >> 5][j] = w;
    }
    __syncthreads();
    if (t < 8){
        float tot = 0.f;
        #pragma unroll
        for (int w = 0; w < 8; w++) tot += red[w][t];
        inv[t] = 1.f / tot;
    }
    __syncthreads();

    #pragma unroll
    for (int j = 0; j < 8; j++){
        float av = e[j] * inv[j];
        g_af[(size_t)b*NL*NL + (size_t)(q0 + j)*NL + t] = __float2half(av);
    }
}

// ---------------------------------------------------------------------------
// K_out: out[b,q,f] = sum_k a[b,q,k]*x[b,k,f]
// fp16 HMMA, 2 terms: a*x_hi + a*x_lo  (a fp16, x split fp16 hi/lo)
// BM=128, BN=128, BK=32; 8 warps 2(M)x4(N), warp tile 64x32.
// A via cp.async (fp16 in gmem); B converted fp32->hi/lo in regs.
// Double-buffered. grid (49, 2, 8), 256 threads.
// ---------------------------------------------------------------------------
// stage layout (bytes): Af 128*40*2=10240 | Bh 32*136*2=8704 | Bl 8704
#define STG    27648
#define OFF_BH 10240
#define OFF_BL 18944
#define K3_SMEM (2*STG)

__global__ __launch_bounds__(256, 2) void k_out(const float* __restrict__ inp,
                                                float* __restrict__ out){
    extern __shared__ char sm[];
    const uint32_t smb = s2u(sm);
    const int t = threadIdx.x, wid = t >> 5, l = t & 31;
    const int lr = l & 15, lc = (l >> 4) << 3;
    const int b  = blockIdx.z;
    const int q0 = blockIdx.y * 128;
    const int f0 = blockIdx.x * 128;
    const int warp_m = wid >> 2, warp_n = wid & 3;   // 2 x 4

    const __half* gaf = g_af + ((size_t)b*NL + q0)*NL;
    const float* gx = inp + (size_t)b*NL*NF + f0;

    // A staging (cp.async 16B): 128 rows x 32 k fp16 = 512 x 16B -> 2 per thread
    const int aR[2] = { (t+0)>>2, (t+256)>>2 };
    const int aC    = (t & 3)*8;
    // B staging: 32 rows x 128 floats = 1024 float4 -> 4 per thread
    int bR[4];
    #pragma unroll
    for (int i = 0; i < 4; i++) bR[i] = (t + i*256) >> 5;
    const int bC = (t & 31)*4;

    float acc[4][4][4];
    #pragma unroll
    for (int mt = 0; mt < 4; mt++)
        #pragma unroll
        for (int ng = 0; ng < 4; ng++)
            #pragma unroll
            for (int k = 0; k < 4; k++) acc[mt][ng][k] = 0.f;

    float4 bv[4];

    // ---- prologue: chunk 0 -> stage 0
    {
        #pragma unroll
        for (int i = 0; i < 2; i++)
            cp16(smb + (uint32_t)aR[i]*80 + aC*2, gaf + (size_t)aR[i]*NL + aC);
        cp_commit();
        #pragma unroll
        for (int i = 0; i < 4; i++)
            bv[i] = *(const float4*)(gx + (size_t)bR[i]*NF + bC);
        #pragma unroll
        for (int i = 0; i < 4; i++){
            uint2 h, lo; split4h(bv[i], h, lo);
            *(uint2*)(sm + OFF_BH + (size_t)bR[i]*272 + bC*2) = h;
            *(uint2*)(sm + OFF_BL + (size_t)bR[i]*272 + bC*2) = lo;
        }
        cp_wait0();
    }
    __syncthreads();

    for (int c = 0; c < 8; c++){
        const int cur = c & 1;
        const uint32_t base = smb + cur*STG;

        if (c < 7){
            const int k0 = (c+1)*32;
            const uint32_t nxt = smb + (1-cur)*STG;
            #pragma unroll
            for (int i = 0; i < 2; i++)
                cp16(nxt + (uint32_t)aR[i]*80 + aC*2, gaf + (size_t)aR[i]*NL + k0 + aC);
            cp_commit();
            #pragma unroll
            for (int i = 0; i < 4; i++)
                bv[i] = *(const float4*)(gx + (size_t)(k0 + bR[i])*NF + bC);
        }

        #pragma unroll
        for (int ks = 0; ks < 32; ks += 16){
            uint32_t fbh[8], fbl[8];
            ldsm4t(fbh + 0, base + OFF_BH + ((ks + lr)*136 + warp_n*32 + 0  + lc)*2);
            ldsm4t(fbh + 4, base + OFF_BH + ((ks + lr)*136 + warp_n*32 + 16 + lc)*2);
            ldsm4t(fbl + 0, base + OFF_BL + ((ks + lr)*136 + warp_n*32 + 0  + lc)*2);
            ldsm4t(fbl + 4, base + OFF_BL + ((ks + lr)*136 + warp_n*32 + 16 + lc)*2);
            #pragma unroll
            for (int mt = 0; mt < 4; mt++){
                uint32_t fa[4];
                ldsm4(fa, base + ((warp_m*64 + mt*16 + lr)*40 + ks + lc)*2);
                #pragma unroll
                for (int ng = 0; ng < 4; ng++){
                    mma_f16(acc[mt][ng], fa, fbh[ng*2], fbh[ng*2+1]);
                    mma_f16(acc[mt][ng], fa, fbl[ng*2], fbl[ng*2+1]);
                }
            }
        }

        if (c < 7){
            char* sn = sm + (1-cur)*STG;
            #pragma unroll
            for (int i = 0; i < 4; i++){
                uint2 h, lo; split4h(bv[i], h, lo);
                *(uint2*)(sn + OFF_BH + (size_t)bR[i]*272 + bC*2) = h;
                *(uint2*)(sn + OFF_BL + (size_t)bR[i]*272 + bC*2) = lo;
            }
            cp_wait0();
        }
        __syncthreads();
    }

    // epilogue
    const int c0 = (l & 3)*2;
    #pragma unroll
    for (int mt = 0; mt < 4; mt++){
        const int row = q0 + warp_m*64 + mt*16 + (l >> 2);
        #pragma unroll
        for (int ng = 0; ng < 4; ng++){
            const int col = f0 + warp_n*32 + ng*8 + c0;
            *(float2*)&out[((size_t)(b*NL + row))*NF + col] =
                make_float2(acc[mt][ng][0], acc[mt][ng][1]);
            *(float2*)&out[((size_t)(b*NL + row + 8))*NF + col] =
                make_float2(acc[mt][ng][2], acc[mt][ng][3]);
        }
    }
}

// ---------------------------------------------------------------------------
extern "C" void kernel_launch(void* const* d_in, const int* in_sizes, int n_in,
                              void* d_out, int out_size){
    const float* inp = (const float*)d_in[0];
    const float* Wt  = (const float*)d_in[1];
    const float* bh  = (const float*)d_in[2];
    const float* Wa  = (const float*)d_in[3];
    const float* ba  = (const float*)d_in[4];
    float* out = (float*)d_out;

    static bool attr_set = false;
    if (!attr_set){
        cudaFuncSetAttribute(k_out, cudaFuncAttributeMaxDynamicSharedMemorySize, K3_SMEM);
        attr_set = true;
    }

    k_proj<<<dim3(16, KSPLIT), 256>>>(inp, Wt);
    k_pred<<<NB*NL*NU/256, 256>>>();
    k_attn<<<dim3(NL/8, NB), 256>>>(bh, Wa, ba);
    k_out<<<dim3(NF/128, NL/128, NB), 256, K3_SMEM>>>(inp, out);
}

// round 7
// speedup vs baseline: 4.3659x; 1.2600x over previous
#include <cuda_runtime.h>
#include <cuda_fp16.h>
#include <cstdint>

#define NB 8
#define NL 256
#define NF 6272
#define NU 32
#define KSPLIT 14

// Scratch (no cudaMalloc allowed)
__device__ float g_p[NB*NL*NU];                      // reduced projections
__device__ float g_pp[KSPLIT*NB*NL*NU];              // projection partials (deterministic)
__device__ __half g_af[NB*NL*NL];                    // a (softmax) fp16 [b][q][k]
__device__ __half g_xh[(size_t)NB*NL*NF];            // inputs fp16 [b][k][f] (written by k_proj)

// ---------------------------------------------------------------------------
// helpers
// ---------------------------------------------------------------------------
__device__ __forceinline__ uint32_t s2u(const void* p){
    uint32_t a;
    asm("{ .reg .u64 t; cvta.to.shared.u64 t, %1; cvt.u32.u64 %0, t; }" : "=r"(a) : "l"(p));
    return a;
}
__device__ __forceinline__ float tanh_approx(float x){
    float y; asm("tanh.approx.f32 %0, %1;" : "=f"(y) : "f"(x)); return y;
}
__device__ __forceinline__ void ldsm4(uint32_t r[4], uint32_t a){
    asm volatile("ldmatrix.sync.aligned.m8n8.x4.shared.b16 {%0,%1,%2,%3}, [%4];"
                 : "=r"(r[0]), "=r"(r[1]), "=r"(r[2]), "=r"(r[3]) : "r"(a));
}
__device__ __forceinline__ void ldsm4t(uint32_t r[4], uint32_t a){
    asm volatile("ldmatrix.sync.aligned.m8n8.x4.trans.shared.b16 {%0,%1,%2,%3}, [%4];"
                 : "=r"(r[0]), "=r"(r[1]), "=r"(r[2]), "=r"(r[3]) : "r"(a));
}
__device__ __forceinline__ void mma_f16(float c[4], const uint32_t a[4], uint32_t b0, uint32_t b1){
    asm volatile(
        "mma.sync.aligned.m16n8k16.row.col.f32.f16.f16.f32 "
        "{%0,%1,%2,%3}, {%4,%5,%6,%7}, {%8,%9}, {%0,%1,%2,%3};"
        : "+f"(c[0]), "+f"(c[1]), "+f"(c[2]), "+f"(c[3])
        : "r"(a[0]), "r"(a[1]), "r"(a[2]), "r"(a[3]), "r"(b0), "r"(b1));
}
__device__ __forceinline__ uint2 cvt4h(float4 v){
    __half h[4];
    h[0] = __float2half(v.x); h[1] = __float2half(v.y);
    h[2] = __float2half(v.z); h[3] = __float2half(v.w);
    return *(uint2*)h;
}
__device__ __forceinline__ void cp16(uint32_t dst, const void* src){
    asm volatile("cp.async.ca.shared.global [%0], [%1], 16;" :: "r"(dst), "l"(src));
}
__device__ __forceinline__ void cp_commit(){ asm volatile("cp.async.commit_group;"); }
__device__ __forceinline__ void cp_wait1(){ asm volatile("cp.async.wait_group 1;"); }

// ---------------------------------------------------------------------------
// K_proj: p_partial[by] = x[rows, fchunk] @ Wt[fchunk, 32]  (fp16 HMMA, 1 term)
// Also writes g_xh (inputs as fp16) as a byproduct.
// grid (16, 14), 256 threads.
// ---------------------------------------------------------------------------
__global__ __launch_bounds__(256) void k_proj(const float* __restrict__ inp,
                                              const float* __restrict__ Wt){
    __shared__ __half Ah[128][40];
    __shared__ __half Bh[32][40];
    const int t = threadIdx.x, wid = t >> 5, l = t & 31;
    const int lr = l & 15, lc = (l >> 4) << 3;
    const int row0 = blockIdx.x * 128;
    const int fb0  = blockIdx.y * 448;

    const int arR[4] = { (t+0)>>3, (t+256)>>3, (t+512)>>3, (t+768)>>3 };
    const int arC    = (t & 7)*4;
    const int wrR    = t >> 3, wrC = (t & 7)*4;

    float acc[4][4];
    #pragma unroll
    for (int i = 0; i < 4; i++)
        #pragma unroll
        for (int j = 0; j < 4; j++) acc[i][j] = 0.f;

    const uint32_t a_ah = s2u(Ah), a_bh = s2u(Bh);

    float4 xv[4], wv;
    #pragma unroll
    for (int i = 0; i < 4; i++)
        xv[i] = *(const float4*)(inp + (size_t)(row0 + arR[i])*NF + fb0 + arC);
    wv = *(const float4*)(Wt + (size_t)(fb0 + wrR)*NU + wrC);

    for (int s = 0; s < 14; s++){
        const int fb = fb0 + s*32;
        #pragma unroll
        for (int i = 0; i < 4; i++){
            uint2 h = cvt4h(xv[i]);
            *(uint2*)&Ah[arR[i]][arC] = h;
            // write-through: inputs as fp16 for k_out
            *(uint2*)&g_xh[(size_t)(row0 + arR[i])*NF + fb + arC] = h;
        }
        *(uint2*)&Bh[wrR][wrC] = cvt4h(wv);
        __syncthreads();

        if (s < 13){
            const int fbn = fb0 + (s+1)*32;
            #pragma unroll
            for (int i = 0; i < 4; i++)
                xv[i] = *(const float4*)(inp + (size_t)(row0 + arR[i])*NF + fbn + arC);
            wv = *(const float4*)(Wt + (size_t)(fbn + wrR)*NU + wrC);
        }

        #pragma unroll
        for (int ks = 0; ks < 32; ks += 16){
            uint32_t fa[4];
            ldsm4(fa, a_ah + ((wid*16 + lr)*40 + ks + lc)*2);
            uint32_t fb4[8];
            ldsm4t(fb4 + 0, a_bh + ((ks + lr)*40 + 0  + lc)*2);
            ldsm4t(fb4 + 4, a_bh + ((ks + lr)*40 + 16 + lc)*2);
            #pragma unroll
            for (int ng = 0; ng < 4; ng++)
                mma_f16(acc[ng], fa, fb4[ng*2], fb4[ng*2+1]);
        }
        __syncthreads();
    }
    float* pp = g_pp + (size_t)blockIdx.y*NB*NL*NU;
    const int r0 = row0 + wid*16 + (l >> 2);
    const int c0 = (l & 3)*2;
    #pragma unroll
    for (int ng = 0; ng < 4; ng++){
        *(float2*)&pp[(size_t)r0*NU + ng*8 + c0]     = make_float2(acc[ng][0], acc[ng][1]);
        *(float2*)&pp[(size_t)(r0+8)*NU + ng*8 + c0] = make_float2(acc[ng][2], acc[ng][3]);
    }
}

// ---------------------------------------------------------------------------
// K_pred: reduce partials -> g_p
// ---------------------------------------------------------------------------
__global__ __launch_bounds__(256) void k_pred(){
    int i = blockIdx.x*256 + threadIdx.x;
    float s = 0.f;
    #pragma unroll
    for (int j = 0; j < KSPLIT; j++) s += g_pp[(size_t)j*NB*NL*NU + i];
    g_p[i] = s;
}

// ---------------------------------------------------------------------------
// K_attn: block handles (b, 8 queries). grid (32, 8), 256 threads (t = k).
// ---------------------------------------------------------------------------
__global__ __launch_bounds__(256) void k_attn(const float* __restrict__ bh,
                                              const float* __restrict__ Wa,
                                              const float* __restrict__ ba){
    __shared__ float ps[NL][33];
    __shared__ float pqb[8][32];
    __shared__ float was[32];
    __shared__ float red[8][8];
    __shared__ float inv[8];

    const int t = threadIdx.x;
    const int b = blockIdx.y;
    const int q0 = blockIdx.x * 8;
    const float* pb = g_p + b*NL*NU;
    const float ba0 = ba[0];

    #pragma unroll
    for (int i = 0; i < 32; i++){
        int idx = t + i*256;
        ps[idx >> 5][idx & 31] = pb[idx];
    }
    if (t < 32) was[t] = Wa[t];
    {
        int j = t >> 5, u = t & 31;
        pqb[j][u] = pb[(q0 + j)*NU + u] + bh[u];
    }
    __syncthreads();

    float e[8];
    #pragma unroll
    for (int j = 0; j < 8; j++){
        float acc = 0.f;
        #pragma unroll
        for (int u = 0; u < 32; u++)
            acc = fmaf(was[u], tanh_approx(pqb[j][u] + ps[t][u]), acc);
        float alpha = acc + ba0;
        float sg = 1.f / (1.f + __expf(-alpha));
        e[j] = __expf(sg);
    }

    #pragma unroll
    for (int j = 0; j < 8; j++){
        float w = e[j];
        #pragma unroll
        for (int o = 16; o > 0; o >>= 1) w += __shfl_xor_sync(0xffffffffu, w, o);
        if ((t & 31) == 0) red[t >> 5][j] = w;
    }
    __syncthreads();
    if (t < 8){
        float tot = 0.f;
        #pragma unroll
        for (int w = 0; w < 8; w++) tot += red[w][t];
        inv[t] = 1.f / tot;
    }
    __syncthreads();

    #pragma unroll
    for (int j = 0; j < 8; j++)
        g_af[(size_t)b*NL*NL + (size_t)(q0 + j)*NL + t] = __float2half(e[j] * inv[j]);
}

// ---------------------------------------------------------------------------
// K_out: out[b,q,f] = sum_k a[b,q,k]*x[b,k,f]   (single fp16 HMMA term)
// BM=128, BN=128, BK=32; 8 warps 2(M)x4(N), warp tile 64x32.
// Both operands fp16 in gmem -> pure cp.async staging, 3-stage pipeline.
// grid (49, 2, 8), 256 threads.
// ---------------------------------------------------------------------------
// stage layout (bytes): Af 128*40*2 = 10240 | Bf 32*136*2 = 8704  -> 18944
#define STG    18944
#define OFF_B  10240
#define NSTAGE 3
#define K3_SMEM (NSTAGE*STG)

__global__ __launch_bounds__(256, 2) void k_out(float* __restrict__ out){
    extern __shared__ char sm[];
    const uint32_t smb = s2u(sm);
    const int t = threadIdx.x, wid = t >> 5, l = t & 31;
    const int lr = l & 15, lc = (l >> 4) << 3;
    const int b  = blockIdx.z;
    const int q0 = blockIdx.y * 128;
    const int f0 = blockIdx.x * 128;
    const int warp_m = wid >> 2, warp_n = wid & 3;   // 2 x 4

    const __half* gaf = g_af + ((size_t)b*NL + q0)*NL;
    const __half* gx  = g_xh + (size_t)b*NL*NF + f0;

    // A staging: 128 rows x 32 k fp16 = 512 x 16B -> 2 cp16/thread
    const int aR[2] = { (t+0)>>2, (t+256)>>2 };
    const int aC    = (t & 3)*8;                 // halves (16B)
    // B staging: 32 rows x 128 f fp16 = 512 x 16B -> 2 cp16/thread
    const int bRr[2] = { (t+0)>>4, (t+256)>>4 };
    const int bCc    = (t & 15)*8;               // halves (16B)

    float acc[4][4][4];
    #pragma unroll
    for (int mt = 0; mt < 4; mt++)
        #pragma unroll
        for (int ng = 0; ng < 4; ng++)
            #pragma unroll
            for (int k = 0; k < 4; k++) acc[mt][ng][k] = 0.f;

    // ---- prologue: issue stages for chunks 0 and 1
    #pragma unroll
    for (int c = 0; c < 2; c++){
        const uint32_t st = smb + c*STG;
        const int k0 = c*32;
        #pragma unroll
        for (int i = 0; i < 2; i++){
            cp16(st + (uint32_t)aR[i]*80 + aC*2,          gaf + (size_t)aR[i]*NL + k0 + aC);
            cp16(st + OFF_B + (uint32_t)bRr[i]*272 + bCc*2, gx + (size_t)(k0 + bRr[i])*NF + bCc);
        }
        cp_commit();
    }

    for (int c = 0; c < 8; c++){
        cp_wait1();            // stage c complete (<=1 group outstanding)
        __syncthreads();

        if (c + 2 < 8){
            const uint32_t st = smb + ((c+2) % NSTAGE)*STG;
            const int k0 = (c+2)*32;
            #pragma unroll
            for (int i = 0; i < 2; i++){
                cp16(st + (uint32_t)aR[i]*80 + aC*2,          gaf + (size_t)aR[i]*NL + k0 + aC);
                cp16(st + OFF_B + (uint32_t)bRr[i]*272 + bCc*2, gx + (size_t)(k0 + bRr[i])*NF + bCc);
            }
        }
        cp_commit();

        const uint32_t base = smb + (c % NSTAGE)*STG;
        #pragma unroll
        for (int ks = 0; ks < 32; ks += 16){
            uint32_t fb4[8];
            ldsm4t(fb4 + 0, base + OFF_B + ((ks + lr)*136 + warp_n*32 + 0  + lc)*2);
            ldsm4t(fb4 + 4, base + OFF_B + ((ks + lr)*136 + warp_n*32 + 16 + lc)*2);
            #pragma unroll
            for (int mt = 0; mt < 4; mt++){
                uint32_t fa[4];
                ldsm4(fa, base + ((warp_m*64 + mt*16 + lr)*40 + ks + lc)*2);
                #pragma unroll
                for (int ng = 0; ng < 4; ng++)
                    mma_f16(acc[mt][ng], fa, fb4[ng*2], fb4[ng*2+1]);
            }
        }
    }

    // epilogue
    const int c0 = (l & 3)*2;
    #pragma unroll
    for (int mt = 0; mt < 4; mt++){
        const int row = q0 + warp_m*64 + mt*16 + (l >> 2);
        #pragma unroll
        for (int ng = 0; ng < 4; ng++){
            const int col = f0 + warp_n*32 + ng*8 + c0;
            *(float2*)&out[((size_t)(b*NL + row))*NF + col] =
                make_float2(acc[mt][ng][0], acc[mt][ng][1]);
            *(float2*)&out[((size_t)(b*NL + row + 8))*NF + col] =
                make_float2(acc[mt][ng][2], acc[mt][ng][3]);
        }
    }
}

// ---------------------------------------------------------------------------
extern "C" void kernel_launch(void* const* d_in, const int* in_sizes, int n_in,
                              void* d_out, int out_size){
    const float* inp = (const float*)d_in[0];
    const float* Wt  = (const float*)d_in[1];
    const float* bh  = (const float*)d_in[2];
    const float* Wa  = (const float*)d_in[3];
    const float* ba  = (const float*)d_in[4];
    float* out = (float*)d_out;

    static bool attr_set = false;
    if (!attr_set){
        cudaFuncSetAttribute(k_out, cudaFuncAttributeMaxDynamicSharedMemorySize, K3_SMEM);
        attr_set = true;
    }

    k_proj<<<dim3(16, KSPLIT), 256>>>(inp, Wt);
    k_pred<<<NB*NL*NU/256, 256>>>();
    k_attn<<<dim3(NL/8, NB), 256>>>(bh, Wa, ba);
    k_out<<<dim3(NF/128, NL/128, NB), 256, K3_SMEM>>>(out);
}